// round 1
// baseline (speedup 1.0000x reference)
#include <cuda_runtime.h>
#include <cuda_bf16.h>
#include <cstdint>

// SelfAttention_82403242541160
// out[b,k] = sum_q softmax(Q Kt / 16)[q,:] @ V  -> collapses to sum_n w_n * V[n,k]
// with w_n = sum_q exp(s_qn) / Z_q,  Z_q = sum_n exp(s_qn).
//
// Pipeline:
//   init:        zero Z and out
//   qkv_gemm:    X = td + ue (on the fly); Q/K/V = X @ W{q,k,v}   (fp32 tiled GEMM)
//   qk_exp:      S = Q Kt / 16, P = exp(S) stored bf16, Z_q += rowsum (atomics)
//   colsum:      w_n = sum_q P[q,n] * (1/Z_q)
//   out_gemv:    out[b,k] = sum_n w_n * V[n,k]   (atomicAdd across n-chunks)

#define BB 32
#define NN 2048
#define DD 256

__device__ float g_Q[(size_t)BB * NN * DD];             // 64 MB
__device__ float g_K[(size_t)BB * NN * DD];             // 64 MB
__device__ float g_V[(size_t)BB * NN * DD];             // 64 MB
__device__ __nv_bfloat16 g_P[(size_t)BB * NN * NN];     // 256 MB
__device__ float g_Z[BB * NN];
__device__ float g_Wc[BB * NN];

// ---------------------------------------------------------------------------
__global__ void __launch_bounds__(256) init_kernel(float* __restrict__ out) {
    int i = blockIdx.x * 256 + threadIdx.x;
    if (i < BB * NN) g_Z[i] = 0.0f;
    if (i < BB * DD) out[i] = 0.0f;
}

// ---------------------------------------------------------------------------
// Fused add + QKV GEMM.  M = B*N = 65536 rows, Kdim = 256, 3 weight matrices.
// Block tile 128x128, BK=8, 256 threads, 8x8 per thread.
// grid = (6, 512): blockIdx.x selects (matrix, 128-col half); blockIdx.y = row tile.
__global__ void __launch_bounds__(256) qkv_gemm(
    const float* __restrict__ A1, const float* __restrict__ A2,
    const float* __restrict__ Wq, const float* __restrict__ Wk,
    const float* __restrict__ Wv) {
    __shared__ float As[8][128];
    __shared__ float Bs[8][128];

    int ct = blockIdx.x;
    int mt = blockIdx.y;
    int mat = ct >> 1;
    int cb  = (ct & 1) * 128;
    const float* W = (mat == 0) ? Wq : ((mat == 1) ? Wk : Wv);
    float*       O = (mat == 0) ? g_Q : ((mat == 1) ? g_K : g_V);

    int tid = threadIdx.x;
    int tx = tid & 15, ty = tid >> 4;
    int arow = tid >> 1, acol = (tid & 1) * 4;
    int brow = tid >> 5, bcol = (tid & 31) * 4;

    float acc[8][8];
#pragma unroll
    for (int i = 0; i < 8; i++)
#pragma unroll
        for (int j = 0; j < 8; j++) acc[i][j] = 0.0f;

    size_t aBase = (size_t)(mt * 128 + arow) * DD;

    for (int k0 = 0; k0 < DD; k0 += 8) {
        float4 a1 = *(const float4*)(A1 + aBase + k0 + acol);
        float4 a2 = *(const float4*)(A2 + aBase + k0 + acol);
        As[acol + 0][arow] = a1.x + a2.x;
        As[acol + 1][arow] = a1.y + a2.y;
        As[acol + 2][arow] = a1.z + a2.z;
        As[acol + 3][arow] = a1.w + a2.w;
        *(float4*)&Bs[brow][bcol] =
            *(const float4*)(W + (size_t)(k0 + brow) * DD + cb + bcol);
        __syncthreads();
#pragma unroll
        for (int kk = 0; kk < 8; kk++) {
            float a[8], bb[8];
            *(float4*)(a)      = *(float4*)&As[kk][ty * 8];
            *(float4*)(a + 4)  = *(float4*)&As[kk][ty * 8 + 4];
            *(float4*)(bb)     = *(float4*)&Bs[kk][tx * 8];
            *(float4*)(bb + 4) = *(float4*)&Bs[kk][tx * 8 + 4];
#pragma unroll
            for (int i = 0; i < 8; i++)
#pragma unroll
                for (int j = 0; j < 8; j++) acc[i][j] += a[i] * bb[j];
        }
        __syncthreads();
    }

#pragma unroll
    for (int i = 0; i < 8; i++) {
        size_t row = (size_t)(mt * 128 + ty * 8 + i);
        float4 o0 = make_float4(acc[i][0], acc[i][1], acc[i][2], acc[i][3]);
        float4 o1 = make_float4(acc[i][4], acc[i][5], acc[i][6], acc[i][7]);
        *(float4*)(O + row * DD + cb + tx * 8)     = o0;
        *(float4*)(O + row * DD + cb + tx * 8 + 4) = o1;
    }
}

// ---------------------------------------------------------------------------
// S = Q Kt / 16, P = exp(S) (bf16), Z_q += rowsum.
// grid = (NN/128 n-tiles, NN/128 q-tiles, BB). Block tile 128x128, BK=8.
__global__ void __launch_bounds__(256) qk_exp_kernel() {
    __shared__ float Qs[8][128];
    __shared__ float Ks[8][128];

    int nt = blockIdx.x, qt = blockIdx.y, b = blockIdx.z;
    int tid = threadIdx.x;
    int tx = tid & 15, ty = tid >> 4;
    int lrow = tid >> 1, lcol = (tid & 1) * 4;

    const float* Qp = g_Q + (size_t)b * NN * DD + (size_t)qt * 128 * DD;
    const float* Kp = g_K + (size_t)b * NN * DD + (size_t)nt * 128 * DD;

    float acc[8][8];
#pragma unroll
    for (int i = 0; i < 8; i++)
#pragma unroll
        for (int j = 0; j < 8; j++) acc[i][j] = 0.0f;

    for (int k0 = 0; k0 < DD; k0 += 8) {
        float4 qa = *(const float4*)(Qp + (size_t)lrow * DD + k0 + lcol);
        float4 ka = *(const float4*)(Kp + (size_t)lrow * DD + k0 + lcol);
        Qs[lcol + 0][lrow] = qa.x; Qs[lcol + 1][lrow] = qa.y;
        Qs[lcol + 2][lrow] = qa.z; Qs[lcol + 3][lrow] = qa.w;
        Ks[lcol + 0][lrow] = ka.x; Ks[lcol + 1][lrow] = ka.y;
        Ks[lcol + 2][lrow] = ka.z; Ks[lcol + 3][lrow] = ka.w;
        __syncthreads();
#pragma unroll
        for (int kk = 0; kk < 8; kk++) {
            float a[8], bb[8];
            *(float4*)(a)      = *(float4*)&Qs[kk][ty * 8];
            *(float4*)(a + 4)  = *(float4*)&Qs[kk][ty * 8 + 4];
            *(float4*)(bb)     = *(float4*)&Ks[kk][tx * 8];
            *(float4*)(bb + 4) = *(float4*)&Ks[kk][tx * 8 + 4];
#pragma unroll
            for (int i = 0; i < 8; i++)
#pragma unroll
                for (int j = 0; j < 8; j++) acc[i][j] += a[i] * bb[j];
        }
        __syncthreads();
    }

    const float scale = 0.0625f;  // 1/sqrt(256)
    __nv_bfloat16* Pp = g_P + (size_t)b * NN * NN +
                        (size_t)(qt * 128 + ty * 8) * NN + nt * 128 + tx * 8;

#pragma unroll
    for (int i = 0; i < 8; i++) {
        float p[8];
        float rs = 0.0f;
#pragma unroll
        for (int j = 0; j < 8; j++) {
            p[j] = __expf(acc[i][j] * scale);
            rs += p[j];
        }
        __nv_bfloat162 v0 = __floats2bfloat162_rn(p[0], p[1]);
        __nv_bfloat162 v1 = __floats2bfloat162_rn(p[2], p[3]);
        __nv_bfloat162 v2 = __floats2bfloat162_rn(p[4], p[5]);
        __nv_bfloat162 v3 = __floats2bfloat162_rn(p[6], p[7]);
        uint4 u;
        u.x = *reinterpret_cast<unsigned*>(&v0);
        u.y = *reinterpret_cast<unsigned*>(&v1);
        u.z = *reinterpret_cast<unsigned*>(&v2);
        u.w = *reinterpret_cast<unsigned*>(&v3);
        *(uint4*)(Pp + (size_t)i * NN) = u;

        // reduce rowsum across the 16 lanes of this row group (lane bits 0..3)
        float v = rs;
        v += __shfl_xor_sync(0xffffffffu, v, 8);
        v += __shfl_xor_sync(0xffffffffu, v, 4);
        v += __shfl_xor_sync(0xffffffffu, v, 2);
        v += __shfl_xor_sync(0xffffffffu, v, 1);
        if ((tid & 15) == 0)
            atomicAdd(&g_Z[b * NN + qt * 128 + ty * 8 + i], v);
    }
}

// ---------------------------------------------------------------------------
// w_n = sum_q P[b,q,n] / Z_q.  grid = (NN/256, BB), 256 threads (one n each).
__global__ void __launch_bounds__(256) colsum_kernel() {
    __shared__ float rz[NN];  // 8 KB
    int b = blockIdx.y;
    int n = blockIdx.x * 256 + threadIdx.x;

    for (int i = threadIdx.x; i < NN; i += 256)
        rz[i] = 1.0f / g_Z[b * NN + i];
    __syncthreads();

    const __nv_bfloat16* Pp = g_P + (size_t)b * NN * NN + n;
    float w = 0.0f;
#pragma unroll 8
    for (int q = 0; q < NN; q++)
        w += __bfloat162float(Pp[(size_t)q * NN]) * rz[q];
    g_Wc[b * NN + n] = w;
}

// ---------------------------------------------------------------------------
// out[b,k] = sum_n w_n * V[b,n,k].  grid = (4, BB): each block does 512 n-rows.
__global__ void __launch_bounds__(256) out_kernel(float* __restrict__ out) {
    __shared__ float ws[512];
    int b = blockIdx.y;
    int n0 = blockIdx.x * 512;

    for (int i = threadIdx.x; i < 512; i += 256)
        ws[i] = g_Wc[b * NN + n0 + i];
    __syncthreads();

    int k = threadIdx.x;
    const float* Vp = g_V + (size_t)b * NN * DD + (size_t)n0 * DD + k;
    float acc = 0.0f;
#pragma unroll 8
    for (int r = 0; r < 512; r++)
        acc += ws[r] * Vp[(size_t)r * DD];
    atomicAdd(&out[b * DD + k], acc);
}

// ---------------------------------------------------------------------------
extern "C" void kernel_launch(void* const* d_in, const int* in_sizes, int n_in,
                              void* d_out, int out_size) {
    const float* td = (const float*)d_in[0];
    const float* ue = (const float*)d_in[1];
    const float* wq = (const float*)d_in[2];
    const float* wk = (const float*)d_in[3];
    const float* wv = (const float*)d_in[4];
    float* out = (float*)d_out;

    init_kernel<<<(BB * NN) / 256, 256>>>(out);
    qkv_gemm<<<dim3(6, (BB * NN) / 128), 256>>>(td, ue, wq, wk, wv);
    qk_exp_kernel<<<dim3(NN / 128, NN / 128, BB), 256>>>();
    colsum_kernel<<<dim3(NN / 256, BB), 256>>>();
    out_kernel<<<dim3(4, BB), 256>>>(out);
}

// round 4
// speedup vs baseline: 5.5240x; 5.5240x over previous
#include <cuda_runtime.h>
#include <cuda_bf16.h>
#include <cuda_fp16.h>
#include <cstdint>

// SelfAttention_82403242541160 — R4: fp16 HMMA attention, V eliminated
// out_b = (sum_n w_n x_n) @ Wv   with  w_n = sum_q P_qn/Z_q,
// P = exp2(Qs K^T) (scale (1/16)*log2e folded into Qs), Z = rowsum(P).
// Attention path fp16 (X, Wq/Wk, Q, K, P); output path fp32 exact.

#define BB 32
#define NN 2048
#define DD 256

__device__ __half g_Xh[(size_t)BB * NN * DD];   // X = td+ue, fp16 (32 MB)
__device__ __half g_Wt[2 * DD * DD];            // Wq^T, Wk^T fp16 [512][256]
__device__ __half g_Qh[(size_t)BB * NN * DD];   // scaled by (1/16)*log2e
__device__ __half g_Kh[(size_t)BB * NN * DD];
__device__ __half g_P [(size_t)BB * NN * NN];   // 256 MB
__device__ float g_Z [BB * NN];
__device__ float g_Wc[BB * NN];
__device__ float g_Y [BB * DD];

// ---------------------------------------------------------------------------
__device__ __forceinline__ uint32_t smem_u32(const void* p) {
    uint32_t a;
    asm("{ .reg .u64 t; cvta.to.shared.u64 t, %1; cvt.u32.u64 %0, t; }"
        : "=r"(a) : "l"(p));
    return a;
}
__device__ __forceinline__ void cp16(uint32_t s, const void* g) {
    asm volatile("cp.async.cg.shared.global [%0], [%1], 16;" :: "r"(s), "l"(g));
}
#define CP_COMMIT() asm volatile("cp.async.commit_group;" ::: "memory")
#define CP_WAIT(n)  asm volatile("cp.async.wait_group %0;" :: "n"(n) : "memory")

__device__ __forceinline__ void ldm_x4(uint32_t addr, uint32_t* r) {
    asm volatile("ldmatrix.sync.aligned.m8n8.x4.shared.b16 {%0,%1,%2,%3}, [%4];"
                 : "=r"(r[0]), "=r"(r[1]), "=r"(r[2]), "=r"(r[3]) : "r"(addr));
}
__device__ __forceinline__ void mma_16816(float* d, const uint32_t* a, const uint32_t* b) {
    asm volatile(
        "mma.sync.aligned.m16n8k16.row.col.f32.f16.f16.f32 "
        "{%0,%1,%2,%3}, {%4,%5,%6,%7}, {%8,%9}, {%0,%1,%2,%3};"
        : "+f"(d[0]), "+f"(d[1]), "+f"(d[2]), "+f"(d[3])
        : "r"(a[0]), "r"(a[1]), "r"(a[2]), "r"(a[3]), "r"(b[0]), "r"(b[1]));
}

// smem tile: 128 rows x 64 halves = 128 B/row; 16B units swizzled u ^= (row&7).
#define STAGE_BYTES 32768           // A(16K) + B(16K)
#define SMEM_DYN    (2 * STAGE_BYTES)

__device__ __forceinline__ void load_stage(
    uint32_t smA, uint32_t smB,
    const __half* __restrict__ Ag, const __half* __restrict__ Bg,
    int k0, int tid) {
#pragma unroll
    for (int i = 0; i < 4; i++) {
        int u_idx = tid + i * 256;            // 0..1023
        int row = u_idx >> 3, u = u_idx & 7;
        uint32_t so = (uint32_t)((row << 7) + ((u ^ (row & 7)) << 4));
        cp16(smA + so, Ag + (size_t)row * DD + k0 + u * 8);
        cp16(smB + so, Bg + (size_t)row * DD + k0 + u * 8);
    }
}

__device__ __forceinline__ void compute_stage(
    uint32_t smA, uint32_t smB, int wm, int wn, int lane, float acc[4][4][4]) {
    int arow = wm * 64 + (lane & 15);
    int ahalf = lane >> 4;
    int brow = wn * 32 + ((lane >> 4) << 3) + (lane & 7);
    int bhalf = (lane >> 3) & 1;
#pragma unroll
    for (int ks = 0; ks < 4; ks++) {
        uint32_t a[4][4];
#pragma unroll
        for (int mf = 0; mf < 4; mf++) {
            int r = arow + mf * 16;
            int u = ks * 2 + ahalf;
            ldm_x4(smA + (r << 7) + ((u ^ (r & 7)) << 4), a[mf]);
        }
        uint32_t b[4][2];
#pragma unroll
        for (int p = 0; p < 2; p++) {
            int r = brow + p * 16;
            int u = ks * 2 + bhalf;
            uint32_t t[4];
            ldm_x4(smB + (r << 7) + ((u ^ (r & 7)) << 4), t);
            b[p * 2][0] = t[0];     b[p * 2][1] = t[1];
            b[p * 2 + 1][0] = t[2]; b[p * 2 + 1][1] = t[3];
        }
#pragma unroll
        for (int mf = 0; mf < 4; mf++)
#pragma unroll
            for (int nf = 0; nf < 4; nf++)
                mma_16816(acc[mf][nf], a[mf], b[nf]);
    }
}

// 128x128x256 tile GEMM. Ag/Bg row-major, stride 256 halves.
__device__ __forceinline__ void gemm_tile(
    const __half* __restrict__ Ag, const __half* __restrict__ Bg,
    char* dsm, int tid, float acc[4][4][4]) {
    uint32_t sm0 = smem_u32(dsm);
    int wid = tid >> 5, lane = tid & 31;
    int wm = wid >> 2, wn = wid & 3;

#pragma unroll
    for (int mf = 0; mf < 4; mf++)
#pragma unroll
        for (int nf = 0; nf < 4; nf++)
#pragma unroll
            for (int j = 0; j < 4; j++) acc[mf][nf][j] = 0.0f;

    load_stage(sm0, sm0 + 16384, Ag, Bg, 0, tid);
    CP_COMMIT();
#pragma unroll
    for (int it = 0; it < 4; it++) {
        uint32_t cs = sm0 + (it & 1) * STAGE_BYTES;
        if (it < 3) {
            uint32_t ns = sm0 + ((it + 1) & 1) * STAGE_BYTES;
            load_stage(ns, ns + 16384, Ag, Bg, (it + 1) * 64, tid);
            CP_COMMIT();
            CP_WAIT(1);
        } else {
            CP_WAIT(0);
        }
        __syncthreads();
        compute_stage(cs, cs + 16384, wm, wn, lane, acc);
        __syncthreads();
    }
}

// ---------------------------------------------------------------------------
__global__ void __launch_bounds__(256) init_kernel() {
    int i = blockIdx.x * 256 + threadIdx.x;
    if (i < BB * NN) { g_Z[i] = 0.0f; g_Wc[i] = 0.0f; }
    if (i < BB * DD) g_Y[i] = 0.0f;
}

__global__ void __launch_bounds__(256) x_kernel(const float* __restrict__ a,
                                                const float* __restrict__ b) {
    size_t i = (size_t)(blockIdx.x * 256 + threadIdx.x) * 8;
    float4 a0 = *(const float4*)(a + i), a1 = *(const float4*)(a + i + 4);
    float4 b0 = *(const float4*)(b + i), b1 = *(const float4*)(b + i + 4);
    __half2 p0 = __floats2half2_rn(a0.x + b0.x, a0.y + b0.y);
    __half2 p1 = __floats2half2_rn(a0.z + b0.z, a0.w + b0.w);
    __half2 p2 = __floats2half2_rn(a1.x + b1.x, a1.y + b1.y);
    __half2 p3 = __floats2half2_rn(a1.z + b1.z, a1.w + b1.w);
    uint4 u;
    u.x = *(unsigned*)&p0; u.y = *(unsigned*)&p1;
    u.z = *(unsigned*)&p2; u.w = *(unsigned*)&p3;
    *(uint4*)(g_Xh + i) = u;
}

__global__ void __launch_bounds__(256) wt_kernel(const float* __restrict__ wq,
                                                 const float* __restrict__ wk) {
    int i = blockIdx.x * 256 + threadIdx.x;   // m*65536 + n*256 + k
    int m = i >> 16, n = (i >> 8) & 255, k = i & 255;
    const float* w = (m == 0) ? wq : wk;
    g_Wt[i] = __float2half_rn(w[k * DD + n]);
}

// ---------------------------------------------------------------------------
// Q,K GEMMs: grid (4, 512); ct = mat*2 + colhalf.
__global__ void __launch_bounds__(256) qk_proj_kernel() {
    extern __shared__ char dsm[];
    int tid = threadIdx.x, wid = tid >> 5, lane = tid & 31;
    int ct = blockIdx.x, mt = blockIdx.y;

    float acc[4][4][4];
    gemm_tile(g_Xh + (size_t)mt * 128 * DD, g_Wt + (size_t)ct * 128 * DD,
              dsm, tid, acc);

    int wm = wid >> 2, wn = wid & 3;
    int lr = lane >> 2, lc = (lane & 3) * 2;
    int mat = ct >> 1;
    int colbase = (ct & 1) * 128;
    const float QSCALE = 0.09016844f;  // (1/16)*log2(e)
    float sc = (mat == 0) ? QSCALE : 1.0f;
    __half* O = (mat == 0) ? g_Qh : g_Kh;

#pragma unroll
    for (int mf = 0; mf < 4; mf++) {
        size_t r0 = (size_t)mt * 128 + wm * 64 + mf * 16 + lr;
        size_t r1 = r0 + 8;
#pragma unroll
        for (int nf = 0; nf < 4; nf++) {
            int c = colbase + wn * 32 + nf * 8 + lc;
            __half2 v0 = __floats2half2_rn(acc[mf][nf][0] * sc, acc[mf][nf][1] * sc);
            __half2 v1 = __floats2half2_rn(acc[mf][nf][2] * sc, acc[mf][nf][3] * sc);
            *(__half2*)(O + r0 * DD + c) = v0;
            *(__half2*)(O + r1 * DD + c) = v1;
        }
    }
}

// ---------------------------------------------------------------------------
// Qs K^T -> exp2 -> P (fp16) + Z rowsum.  grid (16 nt, 16 qt, 32 b).
__global__ void __launch_bounds__(256) qk_mma_kernel() {
    extern __shared__ char dsm[];
    int tid = threadIdx.x, wid = tid >> 5, lane = tid & 31;
    int nt = blockIdx.x, qt = blockIdx.y, b = blockIdx.z;

    float acc[4][4][4];
    gemm_tile(g_Qh + ((size_t)b * NN + qt * 128) * DD,
              g_Kh + ((size_t)b * NN + nt * 128) * DD, dsm, tid, acc);

    int wm = wid >> 2, wn = wid & 3;
    int lr = lane >> 2, lc = (lane & 3) * 2;

#pragma unroll
    for (int mf = 0; mf < 4; mf++) {
        int q0 = qt * 128 + wm * 64 + mf * 16 + lr;
        int q1 = q0 + 8;
        float z0 = 0.0f, z1 = 0.0f;
#pragma unroll
        for (int nf = 0; nf < 4; nf++) {
            int c = nt * 128 + wn * 32 + nf * 8 + lc;
            __half2 p0 = h2exp2(__floats2half2_rn(acc[mf][nf][0], acc[mf][nf][1]));
            __half2 p1 = h2exp2(__floats2half2_rn(acc[mf][nf][2], acc[mf][nf][3]));
            *(__half2*)(g_P + ((size_t)b * NN + q0) * NN + c) = p0;
            *(__half2*)(g_P + ((size_t)b * NN + q1) * NN + c) = p1;
            float2 f0 = __half22float2(p0), f1 = __half22float2(p1);
            z0 += f0.x + f0.y;
            z1 += f1.x + f1.y;
        }
        z0 += __shfl_xor_sync(0xffffffffu, z0, 1);
        z0 += __shfl_xor_sync(0xffffffffu, z0, 2);
        z1 += __shfl_xor_sync(0xffffffffu, z1, 1);
        z1 += __shfl_xor_sync(0xffffffffu, z1, 2);
        if ((lane & 3) == 0) {
            atomicAdd(&g_Z[b * NN + q0], z0);
            atomicAdd(&g_Z[b * NN + q1], z1);
        }
    }
}

// ---------------------------------------------------------------------------
// w_n += sum over 256-q chunk of P/Z.  grid (8, 32); thread owns 8 n (uint4).
__global__ void __launch_bounds__(256) colsum_kernel() {
    __shared__ float rz[256];
    int b = blockIdx.y;
    int q0 = blockIdx.x * 256;
    int tid = threadIdx.x;

    rz[tid] = 1.0f / g_Z[b * NN + q0 + tid];
    __syncthreads();

    int n0 = tid * 8;
    float w[8];
#pragma unroll
    for (int j = 0; j < 8; j++) w[j] = 0.0f;

    const __half* Pb = g_P + ((size_t)b * NN + q0) * NN + n0;
#pragma unroll 4
    for (int q = 0; q < 256; q++) {
        uint4 u = *(const uint4*)(Pb + (size_t)q * NN);
        float rzq = rz[q];
        const __half2* h = (const __half2*)&u;
#pragma unroll
        for (int j = 0; j < 4; j++) {
            float2 f = __half22float2(h[j]);
            w[2 * j]     += f.x * rzq;
            w[2 * j + 1] += f.y * rzq;
        }
    }
#pragma unroll
    for (int j = 0; j < 8; j++)
        atomicAdd(&g_Wc[b * NN + n0 + j], w[j]);
}

// ---------------------------------------------------------------------------
// y[b,d] += sum over n-chunk of w_n * (td+ue)[b,n,d].  grid (4, 32).
__global__ void __launch_bounds__(256) y_kernel(const float* __restrict__ td,
                                                const float* __restrict__ ue) {
    __shared__ float ws[512];
    int b = blockIdx.y;
    int n0 = blockIdx.x * 512;
    for (int i = threadIdx.x; i < 512; i += 256)
        ws[i] = g_Wc[b * NN + n0 + i];
    __syncthreads();

    int d = threadIdx.x;
    size_t base = ((size_t)b * NN + n0) * DD + d;
    float acc = 0.0f;
#pragma unroll 8
    for (int r = 0; r < 512; r++) {
        size_t idx = base + (size_t)r * DD;
        acc += ws[r] * (td[idx] + ue[idx]);
    }
    atomicAdd(&g_Y[b * DD + d], acc);
}

// ---------------------------------------------------------------------------
// out[b,k] = sum_d y[b,d] * wv[d,k].  grid 32, fp32 exact.
__global__ void __launch_bounds__(256) out_kernel(const float* __restrict__ wv,
                                                  float* __restrict__ out) {
    __shared__ float ys[DD];
    int b = blockIdx.x, k = threadIdx.x;
    ys[k] = g_Y[b * DD + k];
    __syncthreads();
    float acc = 0.0f;
#pragma unroll 8
    for (int d = 0; d < DD; d++)
        acc += ys[d] * wv[d * DD + k];
    out[b * DD + k] = acc;
}

// ---------------------------------------------------------------------------
extern "C" void kernel_launch(void* const* d_in, const int* in_sizes, int n_in,
                              void* d_out, int out_size) {
    const float* td = (const float*)d_in[0];
    const float* ue = (const float*)d_in[1];
    const float* wq = (const float*)d_in[2];
    const float* wk = (const float*)d_in[3];
    const float* wv = (const float*)d_in[4];
    float* out = (float*)d_out;

    cudaFuncSetAttribute(qk_proj_kernel,
                         cudaFuncAttributeMaxDynamicSharedMemorySize, SMEM_DYN);
    cudaFuncSetAttribute(qk_mma_kernel,
                         cudaFuncAttributeMaxDynamicSharedMemorySize, SMEM_DYN);

    init_kernel<<<(BB * NN) / 256, 256>>>();
    x_kernel<<<(size_t)BB * NN * DD / (256 * 8), 256>>>(td, ue);
    wt_kernel<<<2 * DD * DD / 256, 256>>>(wq, wk);
    qk_proj_kernel<<<dim3(4, (BB * NN) / 128), 256, SMEM_DYN>>>();
    qk_mma_kernel<<<dim3(NN / 128, NN / 128, BB), 256, SMEM_DYN>>>();
    colsum_kernel<<<dim3(NN / 256, BB), 256>>>();
    y_kernel<<<dim3(4, BB), 256>>>(td, ue);
    out_kernel<<<BB, 256>>>(wv, out);
}

// round 6
// speedup vs baseline: 6.3213x; 1.1443x over previous
#include <cuda_runtime.h>
#include <cuda_fp16.h>
#include <cstdint>

// SelfAttention_82403242541160 — R6 (= R5 resubmit after infra flake):
// 3-stage cp.async pipeline, single sync/chunk
// out_b = (sum_n w_n x_n) @ Wv,  w_n = sum_q P_qn/Z_q,
// P = exp2(Qs K^T) with (1/16)*log2e folded into Qs, Z = rowsum(P).

#define BB 32
#define NN 2048
#define DD 256

__device__ __half g_Xh[(size_t)BB * NN * DD];
__device__ __half g_Wt[2 * DD * DD];            // Wq^T, Wk^T fp16 [512][256]
__device__ __half g_Qh[(size_t)BB * NN * DD];
__device__ __half g_Kh[(size_t)BB * NN * DD];
__device__ __half g_P [(size_t)BB * NN * NN];   // 256 MB
__device__ float g_Z [BB * NN];
__device__ float g_Wc[BB * NN];
__device__ float g_Y [BB * DD];

// ---------------------------------------------------------------------------
__device__ __forceinline__ uint32_t smem_u32(const void* p) {
    uint32_t a;
    asm("{ .reg .u64 t; cvta.to.shared.u64 t, %1; cvt.u32.u64 %0, t; }"
        : "=r"(a) : "l"(p));
    return a;
}
__device__ __forceinline__ void cp16(uint32_t s, const void* g) {
    asm volatile("cp.async.cg.shared.global [%0], [%1], 16;" :: "r"(s), "l"(g));
}
#define CP_COMMIT() asm volatile("cp.async.commit_group;" ::: "memory")
#define CP_WAIT(n)  asm volatile("cp.async.wait_group %0;" :: "n"(n) : "memory")

__device__ __forceinline__ void ldm_x4(uint32_t addr, uint32_t* r) {
    asm volatile("ldmatrix.sync.aligned.m8n8.x4.shared.b16 {%0,%1,%2,%3}, [%4];"
                 : "=r"(r[0]), "=r"(r[1]), "=r"(r[2]), "=r"(r[3]) : "r"(addr));
}
__device__ __forceinline__ void mma_16816(float* d, const uint32_t* a, const uint32_t* b) {
    asm volatile(
        "mma.sync.aligned.m16n8k16.row.col.f32.f16.f16.f32 "
        "{%0,%1,%2,%3}, {%4,%5,%6,%7}, {%8,%9}, {%0,%1,%2,%3};"
        : "+f"(d[0]), "+f"(d[1]), "+f"(d[2]), "+f"(d[3])
        : "r"(a[0]), "r"(a[1]), "r"(a[2]), "r"(a[3]), "r"(b[0]), "r"(b[1]));
}

// smem stage: A(128x64h) + B(128x64h), 128 B/row, 16B units swizzled u ^= (row&7)
#define STAGE_BYTES 32768
#define SMEM_DYN    (3 * STAGE_BYTES)

__device__ __forceinline__ void load_stage(
    uint32_t st, const __half* __restrict__ Ag, const __half* __restrict__ Bg,
    int k0, int tid) {
#pragma unroll
    for (int i = 0; i < 4; i++) {
        int u_idx = tid + i * 256;            // 0..1023
        int row = u_idx >> 3, u = u_idx & 7;
        uint32_t so = (uint32_t)((row << 7) + ((u ^ (row & 7)) << 4));
        cp16(st + so, Ag + (size_t)row * DD + k0 + u * 8);
        cp16(st + 16384 + so, Bg + (size_t)row * DD + k0 + u * 8);
    }
}

__device__ __forceinline__ void compute_stage(
    uint32_t smA, uint32_t smB, int wm, int wn, int lane, float acc[4][4][4]) {
    int arow = wm * 64 + (lane & 15);
    int ahalf = lane >> 4;
    int brow = wn * 32 + ((lane >> 4) << 3) + (lane & 7);
    int bhalf = (lane >> 3) & 1;
#pragma unroll
    for (int ks = 0; ks < 4; ks++) {
        uint32_t a[4][4];
#pragma unroll
        for (int mf = 0; mf < 4; mf++) {
            int r = arow + mf * 16;
            int u = ks * 2 + ahalf;
            ldm_x4(smA + (r << 7) + ((u ^ (r & 7)) << 4), a[mf]);
        }
        uint32_t b[4][2];
#pragma unroll
        for (int p = 0; p < 2; p++) {
            int r = brow + p * 16;
            int u = ks * 2 + bhalf;
            uint32_t t[4];
            ldm_x4(smB + (r << 7) + ((u ^ (r & 7)) << 4), t);
            b[p * 2][0] = t[0];     b[p * 2][1] = t[1];
            b[p * 2 + 1][0] = t[2]; b[p * 2 + 1][1] = t[3];
        }
#pragma unroll
        for (int mf = 0; mf < 4; mf++)
#pragma unroll
            for (int nf = 0; nf < 4; nf++)
                mma_16816(acc[mf][nf], a[mf], b[nf]);
    }
}

// 128x128x256 tile GEMM, 3-buffer pipeline, one syncthreads per K-chunk.
__device__ __forceinline__ void gemm_tile(
    const __half* __restrict__ Ag, const __half* __restrict__ Bg,
    char* dsm, int tid, float acc[4][4][4]) {
    uint32_t sm0 = smem_u32(dsm);
    int wid = tid >> 5, lane = tid & 31;
    int wm = wid >> 2, wn = wid & 3;

#pragma unroll
    for (int mf = 0; mf < 4; mf++)
#pragma unroll
        for (int nf = 0; nf < 4; nf++)
#pragma unroll
            for (int j = 0; j < 4; j++) acc[mf][nf][j] = 0.0f;

    load_stage(sm0, Ag, Bg, 0, tid);
    CP_COMMIT();
    load_stage(sm0 + STAGE_BYTES, Ag, Bg, 64, tid);
    CP_COMMIT();

#pragma unroll
    for (int it = 0; it < 4; it++) {
        if (it < 3) { CP_WAIT(1); } else { CP_WAIT(0); }
        __syncthreads();
        if (it < 2) {
            load_stage(sm0 + ((it + 2) % 3) * STAGE_BYTES, Ag, Bg, (it + 2) * 64, tid);
            CP_COMMIT();
        }
        uint32_t cs = sm0 + (it % 3) * STAGE_BYTES;
        compute_stage(cs, cs + 16384, wm, wn, lane, acc);
    }
}

// ---------------------------------------------------------------------------
__global__ void __launch_bounds__(256) init_kernel() {
    int i = blockIdx.x * 256 + threadIdx.x;
    if (i < BB * NN) { g_Z[i] = 0.0f; g_Wc[i] = 0.0f; }
    if (i < BB * DD) g_Y[i] = 0.0f;
}

__global__ void __launch_bounds__(256) x_kernel(const float* __restrict__ a,
                                                const float* __restrict__ b) {
    size_t i = (size_t)(blockIdx.x * 256 + threadIdx.x) * 8;
    float4 a0 = *(const float4*)(a + i), a1 = *(const float4*)(a + i + 4);
    float4 b0 = *(const float4*)(b + i), b1 = *(const float4*)(b + i + 4);
    __half2 p0 = __floats2half2_rn(a0.x + b0.x, a0.y + b0.y);
    __half2 p1 = __floats2half2_rn(a0.z + b0.z, a0.w + b0.w);
    __half2 p2 = __floats2half2_rn(a1.x + b1.x, a1.y + b1.y);
    __half2 p3 = __floats2half2_rn(a1.z + b1.z, a1.w + b1.w);
    uint4 u;
    u.x = *(unsigned*)&p0; u.y = *(unsigned*)&p1;
    u.z = *(unsigned*)&p2; u.w = *(unsigned*)&p3;
    *(uint4*)(g_Xh + i) = u;
}

__global__ void __launch_bounds__(256) wt_kernel(const float* __restrict__ wq,
                                                 const float* __restrict__ wk) {
    int i = blockIdx.x * 256 + threadIdx.x;   // m*65536 + n*256 + k
    int m = i >> 16, n = (i >> 8) & 255, k = i & 255;
    const float* w = (m == 0) ? wq : wk;
    g_Wt[i] = __float2half_rn(w[k * DD + n]);
}

// ---------------------------------------------------------------------------
// Q,K projections: grid (4, 512); ct = mat*2 + colhalf.
__global__ void __launch_bounds__(256) qk_proj_kernel() {
    extern __shared__ char dsm[];
    int tid = threadIdx.x, wid = tid >> 5, lane = tid & 31;
    int ct = blockIdx.x, mt = blockIdx.y;

    float acc[4][4][4];
    gemm_tile(g_Xh + (size_t)mt * 128 * DD, g_Wt + (size_t)ct * 128 * DD,
              dsm, tid, acc);

    int wm = wid >> 2, wn = wid & 3;
    int lr = lane >> 2, lc = (lane & 3) * 2;
    int mat = ct >> 1;
    int colbase = (ct & 1) * 128;
    const float QSCALE = 0.09016844f;  // (1/16)*log2(e)
    float sc = (mat == 0) ? QSCALE : 1.0f;
    __half* O = (mat == 0) ? g_Qh : g_Kh;

#pragma unroll
    for (int mf = 0; mf < 4; mf++) {
        size_t r0 = (size_t)mt * 128 + wm * 64 + mf * 16 + lr;
        size_t r1 = r0 + 8;
#pragma unroll
        for (int nf = 0; nf < 4; nf++) {
            int c = colbase + wn * 32 + nf * 8 + lc;
            __half2 v0 = __floats2half2_rn(acc[mf][nf][0] * sc, acc[mf][nf][1] * sc);
            __half2 v1 = __floats2half2_rn(acc[mf][nf][2] * sc, acc[mf][nf][3] * sc);
            *(__half2*)(O + r0 * DD + c) = v0;
            *(__half2*)(O + r1 * DD + c) = v1;
        }
    }
}

// ---------------------------------------------------------------------------
// Qs K^T -> exp2 -> P (fp16) + Z rowsum.  grid (16 nt, 16 qt, 32 b).
__global__ void __launch_bounds__(256) qk_mma_kernel() {
    extern __shared__ char dsm[];
    int tid = threadIdx.x, wid = tid >> 5, lane = tid & 31;
    int nt = blockIdx.x, qt = blockIdx.y, b = blockIdx.z;

    float acc[4][4][4];
    gemm_tile(g_Qh + ((size_t)b * NN + qt * 128) * DD,
              g_Kh + ((size_t)b * NN + nt * 128) * DD, dsm, tid, acc);

    int wm = wid >> 2, wn = wid & 3;
    int lr = lane >> 2, lc = (lane & 3) * 2;

#pragma unroll
    for (int mf = 0; mf < 4; mf++) {
        int q0 = qt * 128 + wm * 64 + mf * 16 + lr;
        int q1 = q0 + 8;
        float z0 = 0.0f, z1 = 0.0f;
#pragma unroll
        for (int nf = 0; nf < 4; nf++) {
            int c = nt * 128 + wn * 32 + nf * 8 + lc;
            __half2 p0 = h2exp2(__floats2half2_rn(acc[mf][nf][0], acc[mf][nf][1]));
            __half2 p1 = h2exp2(__floats2half2_rn(acc[mf][nf][2], acc[mf][nf][3]));
            *(__half2*)(g_P + ((size_t)b * NN + q0) * NN + c) = p0;
            *(__half2*)(g_P + ((size_t)b * NN + q1) * NN + c) = p1;
            float2 f0 = __half22float2(p0), f1 = __half22float2(p1);
            z0 += f0.x + f0.y;
            z1 += f1.x + f1.y;
        }
        z0 += __shfl_xor_sync(0xffffffffu, z0, 1);
        z0 += __shfl_xor_sync(0xffffffffu, z0, 2);
        z1 += __shfl_xor_sync(0xffffffffu, z1, 1);
        z1 += __shfl_xor_sync(0xffffffffu, z1, 2);
        if ((lane & 3) == 0) {
            atomicAdd(&g_Z[b * NN + q0], z0);
            atomicAdd(&g_Z[b * NN + q1], z1);
        }
    }
}

// ---------------------------------------------------------------------------
// w_n += sum over 128-q chunk of P/Z.  grid (16, 32); thread owns 8 n (uint4).
__global__ void __launch_bounds__(256) colsum_kernel() {
    __shared__ float rz[128];
    int b = blockIdx.y;
    int q0 = blockIdx.x * 128;
    int tid = threadIdx.x;

    if (tid < 128) rz[tid] = 1.0f / g_Z[b * NN + q0 + tid];
    __syncthreads();

    int n0 = tid * 8;
    float w[8];
#pragma unroll
    for (int j = 0; j < 8; j++) w[j] = 0.0f;

    const __half* Pb = g_P + ((size_t)b * NN + q0) * NN + n0;
#pragma unroll 4
    for (int q = 0; q < 128; q++) {
        uint4 u = *(const uint4*)(Pb + (size_t)q * NN);
        float rzq = rz[q];
        const __half2* h = (const __half2*)&u;
#pragma unroll
        for (int j = 0; j < 4; j++) {
            float2 f = __half22float2(h[j]);
            w[2 * j]     += f.x * rzq;
            w[2 * j + 1] += f.y * rzq;
        }
    }
#pragma unroll
    for (int j = 0; j < 8; j++)
        atomicAdd(&g_Wc[b * NN + n0 + j], w[j]);
}

// ---------------------------------------------------------------------------
// y[b,d] += sum over 256-n chunk of w_n * (td+ue)[b,n,d].  grid (8, 32).
__global__ void __launch_bounds__(256) y_kernel(const float* __restrict__ td,
                                                const float* __restrict__ ue) {
    __shared__ float ws[256];
    int b = blockIdx.y;
    int n0 = blockIdx.x * 256;
    ws[threadIdx.x] = g_Wc[b * NN + n0 + threadIdx.x];
    __syncthreads();

    int d = threadIdx.x;
    size_t base = ((size_t)b * NN + n0) * DD + d;
    float acc = 0.0f;
#pragma unroll 8
    for (int r = 0; r < 256; r++) {
        size_t idx = base + (size_t)r * DD;
        acc += ws[r] * (td[idx] + ue[idx]);
    }
    atomicAdd(&g_Y[b * DD + d], acc);
}

// ---------------------------------------------------------------------------
// out[b,k] = sum_d y[b,d] * wv[d,k].  grid 32, fp32 exact.
__global__ void __launch_bounds__(256) out_kernel(const float* __restrict__ wv,
                                                  float* __restrict__ out) {
    __shared__ float ys[DD];
    int b = blockIdx.x, k = threadIdx.x;
    ys[k] = g_Y[b * DD + k];
    __syncthreads();
    float acc = 0.0f;
#pragma unroll 8
    for (int d = 0; d < DD; d++)
        acc += ys[d] * wv[d * DD + k];
    out[b * DD + k] = acc;
}

// ---------------------------------------------------------------------------
extern "C" void kernel_launch(void* const* d_in, const int* in_sizes, int n_in,
                              void* d_out, int out_size) {
    const float* td = (const float*)d_in[0];
    const float* ue = (const float*)d_in[1];
    const float* wq = (const float*)d_in[2];
    const float* wk = (const float*)d_in[3];
    const float* wv = (const float*)d_in[4];
    float* out = (float*)d_out;

    cudaFuncSetAttribute(qk_proj_kernel,
                         cudaFuncAttributeMaxDynamicSharedMemorySize, SMEM_DYN);
    cudaFuncSetAttribute(qk_mma_kernel,
                         cudaFuncAttributeMaxDynamicSharedMemorySize, SMEM_DYN);

    init_kernel<<<(BB * NN) / 256, 256>>>();
    x_kernel<<<(size_t)BB * NN * DD / (256 * 8), 256>>>(td, ue);
    wt_kernel<<<2 * DD * DD / 256, 256>>>(wq, wk);
    qk_proj_kernel<<<dim3(4, (BB * NN) / 128), 256, SMEM_DYN>>>();
    qk_mma_kernel<<<dim3(NN / 128, NN / 128, BB), 256, SMEM_DYN>>>();
    colsum_kernel<<<dim3(NN / 128, BB), 256>>>();
    y_kernel<<<dim3(8, BB), 256>>>(td, ue);
    out_kernel<<<BB, 256>>>(wv, out);
}